// round 1
// baseline (speedup 1.0000x reference)
#include <cuda_runtime.h>

#define NPATCH 8192
#define NTILES 128
#define NTOT   8320
#define NEDGES 1024
#define INDIM  384
#define DMODEL 256
#define NHEADS 4
#define DHEAD  64
#define MAXDEG 1024

// ---------------- scratch (static device globals; no allocation) ----------------
__device__ float g_hA[NTOT * DMODEL];          // post-GEMM h (per layer)
__device__ float g_hB[NTOT * DMODEL];          // post-layer h (residual output)
__device__ float g_ssrc[NTOT * NHEADS];
__device__ float g_sdst[NTOT * NHEADS];
__device__ float g_sedg[NEDGES * NHEADS];
__device__ float g_m[NEDGES * DMODEL];         // edge messages [E, h, d]
__device__ int   g_edge_mem[NEDGES * MAXDEG];  // CSC: members per edge
__device__ int   g_edge_cnt[NEDGES];
__device__ int   g_node_edges[NTOT * MAXDEG];  // CSR: incident edges per node
__device__ int   g_node_cnt[NTOT];

// ---------------- helpers ----------------
__device__ __forceinline__ float wsum(float v) {
#pragma unroll
    for (int o = 16; o; o >>= 1) v += __shfl_xor_sync(0xffffffffu, v, o);
    return v;
}
__device__ __forceinline__ float wmax(float v) {
#pragma unroll
    for (int o = 16; o; o >>= 1) v = fmaxf(v, __shfl_xor_sync(0xffffffffu, v, o));
    return v;
}
__device__ __forceinline__ float lrelu(float x) { return x >= 0.f ? x : 0.2f * x; }

// ---------------- sparsity extraction (deterministic ordered compaction) ----------------
// CSR: one block per node, scans its contiguous H row.
__global__ void build_csr_kernel(const float* __restrict__ H) {
    const int n = blockIdx.x;
    const int tid = threadIdx.x, lane = tid & 31, wid = tid >> 5;
    const float* row = H + (size_t)n * NEDGES;
    __shared__ int s_base;
    __shared__ int s_wcnt[8];
    if (tid == 0) s_base = 0;
    __syncthreads();
    for (int base = 0; base < NEDGES; base += 256) {
        int e = base + tid;
        bool p = row[e] > 0.f;
        unsigned b = __ballot_sync(0xffffffffu, p);
        if (lane == 0) s_wcnt[wid] = __popc(b);
        __syncthreads();
        int woff = 0;
        for (int w = 0; w < wid; w++) woff += s_wcnt[w];
        if (p) {
            int pos = s_base + woff + __popc(b & ((1u << lane) - 1u));
            g_node_edges[(size_t)n * MAXDEG + pos] = e;
        }
        __syncthreads();
        if (tid == 0) {
            int tot = 0;
            for (int w = 0; w < 8; w++) tot += s_wcnt[w];
            s_base += tot;
        }
        __syncthreads();
    }
    if (tid == 0) g_node_cnt[n] = s_base;
}

// CSC: one block per edge, scans the H column (L2 absorbs the stride).
__global__ void build_csc_kernel(const float* __restrict__ H) {
    const int e = blockIdx.x;
    const int tid = threadIdx.x, lane = tid & 31, wid = tid >> 5;
    __shared__ int s_base;
    __shared__ int s_wcnt[8];
    if (tid == 0) s_base = 0;
    __syncthreads();
    for (int base = 0; base < NTOT; base += 256) {
        int n = base + tid;
        bool p = (n < NTOT) && (H[(size_t)n * NEDGES + e] > 0.f);
        unsigned b = __ballot_sync(0xffffffffu, p);
        if (lane == 0) s_wcnt[wid] = __popc(b);
        __syncthreads();
        int woff = 0;
        for (int w = 0; w < wid; w++) woff += s_wcnt[w];
        if (p) {
            int pos = s_base + woff + __popc(b & ((1u << lane) - 1u));
            if (pos < MAXDEG) g_edge_mem[(size_t)e * MAXDEG + pos] = n;
        }
        __syncthreads();
        if (tid == 0) {
            int tot = 0;
            for (int w = 0; w < 8; w++) tot += s_wcnt[w];
            s_base += tot;
        }
        __syncthreads();
    }
    if (tid == 0) g_edge_cnt[e] = s_base < MAXDEG ? s_base : MAXDEG;
}

// ---------------- GEMM: h = A @ W + node_emb[node_type]  -> g_hA ----------------
// BM=128, BN=64, BK=16, 256 threads, 8x4 per thread. M=8320=65*128, N=256=4*64 exact.
template <int KDIM, bool FIRST>
__global__ void gemm_kernel(const float* __restrict__ A, const float* __restrict__ RO,
                            const float* __restrict__ W, const float* __restrict__ nemb,
                            const int* __restrict__ ntype) {
    __shared__ float As[128][17];
    __shared__ float Bs[16][64];
    const int m0 = blockIdx.x * 128, n0 = blockIdx.y * 64;
    const int tid = threadIdx.x;
    const int tx = tid & 15, ty = tid >> 4;
    float acc[8][4] = {};
    const float* Asrc = FIRST ? A : g_hB;
    for (int k0 = 0; k0 < KDIM; k0 += 16) {
#pragma unroll
        for (int l = 0; l < 8; l++) {
            int idx = tid + l * 256;
            int m = idx >> 4, k = idx & 15;
            int row = m0 + m;
            float v;
            if (FIRST) {
                v = (row < NPATCH) ? Asrc[(size_t)row * KDIM + k0 + k] : RO[k0 + k];
            } else {
                v = Asrc[(size_t)row * KDIM + k0 + k];
            }
            As[m][k] = v;
        }
#pragma unroll
        for (int l = 0; l < 4; l++) {
            int idx = tid + l * 256;
            int k = idx >> 6, n = idx & 63;
            Bs[k][n] = W[(size_t)(k0 + k) * DMODEL + n0 + n];
        }
        __syncthreads();
#pragma unroll
        for (int k = 0; k < 16; k++) {
            float a[8];
#pragma unroll
            for (int i = 0; i < 8; i++) a[i] = As[ty * 8 + i][k];
            float4 bq = *(const float4*)&Bs[k][tx * 4];
            float b[4] = {bq.x, bq.y, bq.z, bq.w};
#pragma unroll
            for (int i = 0; i < 8; i++)
#pragma unroll
                for (int j = 0; j < 4; j++) acc[i][j] += a[i] * b[j];
        }
        __syncthreads();
    }
#pragma unroll
    for (int i = 0; i < 8; i++) {
        int row = m0 + ty * 8 + i;
        int t = ntype[row];
#pragma unroll
        for (int j = 0; j < 4; j++) {
            int col = n0 + tx * 4 + j;
            g_hA[(size_t)row * DMODEL + col] = acc[i][j] + nemb[t * DMODEL + col];
        }
    }
}

// ---------------- per-node attention scalars s_src, s_dst (from g_hA) ----------------
__global__ void compute_s_kernel(const float* __restrict__ asrc, const float* __restrict__ adst) {
    const int warp = (blockIdx.x * blockDim.x + threadIdx.x) >> 5;
    const int lane = threadIdx.x & 31;
    if (warp >= NTOT) return;
    const float* hr = g_hA + (size_t)warp * DMODEL;
#pragma unroll
    for (int hh = 0; hh < NHEADS; hh++) {
        float h0 = hr[hh * 64 + lane], h1 = hr[hh * 64 + 32 + lane];
        float v1 = h0 * asrc[hh * 64 + lane] + h1 * asrc[hh * 64 + 32 + lane];
        float v2 = h0 * adst[hh * 64 + lane] + h1 * adst[hh * 64 + 32 + lane];
        v1 = wsum(v1);
        v2 = wsum(v2);
        if (lane == 0) {
            g_ssrc[warp * 4 + hh] = v1;
            g_sdst[warp * 4 + hh] = v2;
        }
    }
}

// ---------------- stage 1: node -> edge softmax aggregation; also s_edg ----------------
__global__ void stage1_kernel(const float* __restrict__ ebias, const int* __restrict__ etype,
                              const float* __restrict__ aedg) {
    const int e = blockIdx.x;
    const int tid = threadIdx.x, lane = tid & 31, wid = tid >> 5;
    const int cnt = g_edge_cnt[e];
    __shared__ float s_eb[4], s_max[4], s_inv[4];
    __shared__ float s_red[8][4];
    __shared__ int s_n[256];
    __shared__ float s_a[256 * 4];
    if (tid < 4) s_eb[tid] = ebias[etype[e] * 4 + tid];
    __syncthreads();
    const int* mem = g_edge_mem + (size_t)e * MAXDEG;

    // pass 1: per-head max of leaky_relu(s_src + eb)
    float m0 = -1e30f, m1 = -1e30f, m2 = -1e30f, m3 = -1e30f;
    for (int i = tid; i < cnt; i += 256) {
        int n = mem[i];
        float4 ss = *(const float4*)(g_ssrc + n * 4);
        m0 = fmaxf(m0, lrelu(ss.x + s_eb[0]));
        m1 = fmaxf(m1, lrelu(ss.y + s_eb[1]));
        m2 = fmaxf(m2, lrelu(ss.z + s_eb[2]));
        m3 = fmaxf(m3, lrelu(ss.w + s_eb[3]));
    }
    m0 = wmax(m0); m1 = wmax(m1); m2 = wmax(m2); m3 = wmax(m3);
    if (lane == 0) { s_red[wid][0] = m0; s_red[wid][1] = m1; s_red[wid][2] = m2; s_red[wid][3] = m3; }
    __syncthreads();
    if (tid < 4) {
        float m = s_red[0][tid];
        for (int w = 1; w < 8; w++) m = fmaxf(m, s_red[w][tid]);
        s_max[tid] = m;
    }
    __syncthreads();

    // pass 2: per-head sum of exp
    float u0 = 0.f, u1 = 0.f, u2 = 0.f, u3 = 0.f;
    for (int i = tid; i < cnt; i += 256) {
        int n = mem[i];
        float4 ss = *(const float4*)(g_ssrc + n * 4);
        u0 += __expf(lrelu(ss.x + s_eb[0]) - s_max[0]);
        u1 += __expf(lrelu(ss.y + s_eb[1]) - s_max[1]);
        u2 += __expf(lrelu(ss.z + s_eb[2]) - s_max[2]);
        u3 += __expf(lrelu(ss.w + s_eb[3]) - s_max[3]);
    }
    u0 = wsum(u0); u1 = wsum(u1); u2 = wsum(u2); u3 = wsum(u3);
    if (lane == 0) { s_red[wid][0] = u0; s_red[wid][1] = u1; s_red[wid][2] = u2; s_red[wid][3] = u3; }
    __syncthreads();
    if (tid < 4) {
        float t = 0.f;
        for (int w = 0; w < 8; w++) t += s_red[w][tid];
        s_inv[tid] = 1.f / t;
    }
    __syncthreads();

    // pass 3: weighted aggregate  m[e, tid] = sum_members alpha * h[n, tid]
    const int hh = tid >> 6;
    float acc = 0.f;
    for (int base = 0; base < cnt; base += 256) {
        int i = base + tid;
        if (i < cnt) {
            int n = mem[i];
            s_n[tid] = n;
            float4 ss = *(const float4*)(g_ssrc + n * 4);
            s_a[tid * 4 + 0] = __expf(lrelu(ss.x + s_eb[0]) - s_max[0]) * s_inv[0];
            s_a[tid * 4 + 1] = __expf(lrelu(ss.y + s_eb[1]) - s_max[1]) * s_inv[1];
            s_a[tid * 4 + 2] = __expf(lrelu(ss.z + s_eb[2]) - s_max[2]) * s_inv[2];
            s_a[tid * 4 + 3] = __expf(lrelu(ss.w + s_eb[3]) - s_max[3]) * s_inv[3];
        }
        __syncthreads();
        int lim = min(256, cnt - base);
        int j = 0;
        for (; j + 4 <= lim; j += 4) {
            float a0 = s_a[(j + 0) * 4 + hh], a1 = s_a[(j + 1) * 4 + hh];
            float a2 = s_a[(j + 2) * 4 + hh], a3 = s_a[(j + 3) * 4 + hh];
            float v0 = g_hA[(size_t)s_n[j + 0] * DMODEL + tid];
            float v1 = g_hA[(size_t)s_n[j + 1] * DMODEL + tid];
            float v2 = g_hA[(size_t)s_n[j + 2] * DMODEL + tid];
            float v3 = g_hA[(size_t)s_n[j + 3] * DMODEL + tid];
            acc += a0 * v0; acc += a1 * v1; acc += a2 * v2; acc += a3 * v3;
        }
        for (; j < lim; j++) acc += s_a[j * 4 + hh] * g_hA[(size_t)s_n[j] * DMODEL + tid];
        __syncthreads();
    }
    g_m[(size_t)e * DMODEL + tid] = acc;

    // fused s_edg[e,h] = sum_d m[e,h,d]*aedg[h,d]
    float se = acc * aedg[tid];
    se = wsum(se);
    if (lane == 0) s_red[wid][0] = se;
    __syncthreads();
    if (tid < 4) g_sedg[e * 4 + tid] = s_red[2 * tid][0] + s_red[2 * tid + 1][0];
}

// ---------------- stage 2: edge -> node softmax aggregation + ELU + residual ----------------
__global__ void stage2_kernel() {
    const int n = blockIdx.x;
    const int tid = threadIdx.x, lane = tid & 31, wid = tid >> 5;
    const int cnt = g_node_cnt[n];
    __shared__ float s_sd[4], s_max[4], s_inv[4];
    __shared__ float s_red[8][4];
    __shared__ int s_e[256];
    __shared__ float s_b[256 * 4];
    if (tid < 4) s_sd[tid] = g_sdst[n * 4 + tid];
    __syncthreads();
    const int* el = g_node_edges + (size_t)n * MAXDEG;

    float m0 = -1e30f, m1 = -1e30f, m2 = -1e30f, m3 = -1e30f;
    for (int i = tid; i < cnt; i += 256) {
        int e = el[i];
        float4 sg = *(const float4*)(g_sedg + e * 4);
        m0 = fmaxf(m0, lrelu(s_sd[0] + sg.x));
        m1 = fmaxf(m1, lrelu(s_sd[1] + sg.y));
        m2 = fmaxf(m2, lrelu(s_sd[2] + sg.z));
        m3 = fmaxf(m3, lrelu(s_sd[3] + sg.w));
    }
    m0 = wmax(m0); m1 = wmax(m1); m2 = wmax(m2); m3 = wmax(m3);
    if (lane == 0) { s_red[wid][0] = m0; s_red[wid][1] = m1; s_red[wid][2] = m2; s_red[wid][3] = m3; }
    __syncthreads();
    if (tid < 4) {
        float m = s_red[0][tid];
        for (int w = 1; w < 8; w++) m = fmaxf(m, s_red[w][tid]);
        s_max[tid] = m;
    }
    __syncthreads();

    float u0 = 0.f, u1 = 0.f, u2 = 0.f, u3 = 0.f;
    for (int i = tid; i < cnt; i += 256) {
        int e = el[i];
        float4 sg = *(const float4*)(g_sedg + e * 4);
        u0 += __expf(lrelu(s_sd[0] + sg.x) - s_max[0]);
        u1 += __expf(lrelu(s_sd[1] + sg.y) - s_max[1]);
        u2 += __expf(lrelu(s_sd[2] + sg.z) - s_max[2]);
        u3 += __expf(lrelu(s_sd[3] + sg.w) - s_max[3]);
    }
    u0 = wsum(u0); u1 = wsum(u1); u2 = wsum(u2); u3 = wsum(u3);
    if (lane == 0) { s_red[wid][0] = u0; s_red[wid][1] = u1; s_red[wid][2] = u2; s_red[wid][3] = u3; }
    __syncthreads();
    if (tid < 4) {
        float t = 0.f;
        for (int w = 0; w < 8; w++) t += s_red[w][tid];
        s_inv[tid] = 1.f / t;
    }
    __syncthreads();

    const int hh = tid >> 6;
    float acc = 0.f;
    for (int base = 0; base < cnt; base += 256) {
        int i = base + tid;
        if (i < cnt) {
            int e = el[i];
            s_e[tid] = e;
            float4 sg = *(const float4*)(g_sedg + e * 4);
            s_b[tid * 4 + 0] = __expf(lrelu(s_sd[0] + sg.x) - s_max[0]) * s_inv[0];
            s_b[tid * 4 + 1] = __expf(lrelu(s_sd[1] + sg.y) - s_max[1]) * s_inv[1];
            s_b[tid * 4 + 2] = __expf(lrelu(s_sd[2] + sg.z) - s_max[2]) * s_inv[2];
            s_b[tid * 4 + 3] = __expf(lrelu(s_sd[3] + sg.w) - s_max[3]) * s_inv[3];
        }
        __syncthreads();
        int lim = min(256, cnt - base);
        int j = 0;
        for (; j + 4 <= lim; j += 4) {
            float b0 = s_b[(j + 0) * 4 + hh], b1 = s_b[(j + 1) * 4 + hh];
            float b2 = s_b[(j + 2) * 4 + hh], b3 = s_b[(j + 3) * 4 + hh];
            float v0 = g_m[(size_t)s_e[j + 0] * DMODEL + tid];
            float v1 = g_m[(size_t)s_e[j + 1] * DMODEL + tid];
            float v2 = g_m[(size_t)s_e[j + 2] * DMODEL + tid];
            float v3 = g_m[(size_t)s_e[j + 3] * DMODEL + tid];
            acc += b0 * v0; acc += b1 * v1; acc += b2 * v2; acc += b3 * v3;
        }
        for (; j < lim; j++) acc += s_b[j * 4 + hh] * g_m[(size_t)s_e[j] * DMODEL + tid];
        __syncthreads();
    }
    float o = acc > 0.f ? acc : (__expf(acc) - 1.f);        // ELU(alpha=1)
    g_hB[(size_t)n * DMODEL + tid] = o + g_hA[(size_t)n * DMODEL + tid];
}

// ---------------- final layer norm (node rows and bag rows share buffer layout) ----------------
__global__ void ln_kernel(const float* __restrict__ ng, const float* __restrict__ nb,
                          const float* __restrict__ bg, const float* __restrict__ bb,
                          float* __restrict__ out) {
    const int n = blockIdx.x;
    const int tid = threadIdx.x, lane = tid & 31, wid = tid >> 5;
    __shared__ float sred[8];
    __shared__ float s_mean, s_rstd;
    float x = g_hB[(size_t)n * DMODEL + tid];
    float s = wsum(x);
    if (lane == 0) sred[wid] = s;
    __syncthreads();
    if (tid == 0) {
        float t = 0.f;
        for (int w = 0; w < 8; w++) t += sred[w];
        s_mean = t * (1.f / DMODEL);
    }
    __syncthreads();
    float c = x - s_mean;
    float v = wsum(c * c);
    if (lane == 0) sred[wid] = v;
    __syncthreads();
    if (tid == 0) {
        float t = 0.f;
        for (int w = 0; w < 8; w++) t += sred[w];
        s_rstd = rsqrtf(t * (1.f / DMODEL) + 1e-5f);
    }
    __syncthreads();
    const float* g = (n < NPATCH) ? ng : bg;
    const float* b = (n < NPATCH) ? nb : bb;
    out[(size_t)n * DMODEL + tid] = c * s_rstd * g[tid] + b[tid];
}

// ---------------- launcher ----------------
extern "C" void kernel_launch(void* const* d_in, const int* in_sizes, int n_in,
                              void* d_out, int out_size) {
    const float* x_nodes = (const float*)d_in[0];
    const float* ro      = (const float*)d_in[1];
    const int*   ntype   = (const int*)d_in[2];
    const int*   etype   = (const int*)d_in[3];
    const float* H       = (const float*)d_in[4];
    // d_in[5] readout_node_ids == arange(8192, 8320): bag rows are h[8192:] in order
    const float* W0      = (const float*)d_in[6];
    const float* W1      = (const float*)d_in[7];
    const float* nemb    = (const float*)d_in[8];
    const float* asrc    = (const float*)d_in[9];
    const float* adst    = (const float*)d_in[10];
    const float* aedg    = (const float*)d_in[11];
    const float* ebias   = (const float*)d_in[12];
    const float* ngam    = (const float*)d_in[13];
    const float* nbet    = (const float*)d_in[14];
    const float* bgam    = (const float*)d_in[15];
    const float* bbet    = (const float*)d_in[16];
    float* out = (float*)d_out;

    build_csr_kernel<<<NTOT, 256>>>(H);
    build_csc_kernel<<<NEDGES, 256>>>(H);

    for (int layer = 0; layer < 2; layer++) {
        if (layer == 0) {
            gemm_kernel<INDIM, true><<<dim3(NTOT / 128, DMODEL / 64), 256>>>(
                x_nodes, ro, W0, nemb + 0 * 4 * DMODEL, ntype);
        } else {
            gemm_kernel<DMODEL, false><<<dim3(NTOT / 128, DMODEL / 64), 256>>>(
                nullptr, nullptr, W1, nemb + 1 * 4 * DMODEL, ntype);
        }
        compute_s_kernel<<<(NTOT * 32) / 256, 256>>>(asrc + layer * NHEADS * DHEAD,
                                                     adst + layer * NHEADS * DHEAD);
        stage1_kernel<<<NEDGES, 256>>>(ebias + layer * 3 * NHEADS, etype,
                                       aedg + layer * NHEADS * DHEAD);
        stage2_kernel<<<NTOT, 256>>>();
    }

    ln_kernel<<<NTOT, 256>>>(ngam, nbet, bgam, bbet, out);
}